// round 9
// baseline (speedup 1.0000x reference)
#include <cuda_runtime.h>
#include <cuda_bf16.h>
#include <cstdint>

#define C 80
#define KB 32                   // items per tile
#define PITCH_F 88              // f32 per item row (80 + 8 pad) -> bank-conflict-free LDS
#define STAGE_BYTES (KB * PITCH_F * 4)   // 11264
#define NSTAGE 4
#define NWARPS 5
#define NTHREADS 160
#define GRID 740                // 5 CTAs per SM x 148

__device__ float g_cooc[C * C];
__device__ unsigned int g_count;

__global__ __launch_bounds__(NTHREADS, 5)
void fused_kernel(const float* __restrict__ label,
                  const float* __restrict__ pre_adj,
                  float* __restrict__ out, int batch) {
    __shared__ __align__(16) unsigned char sbuf[NSTAGE][STAGE_BYTES];  // f32 [item][class] tiles
    __shared__ float red[NWARPS];
    __shared__ int s_last;

    const int tid  = threadIdx.x;
    const int warp = tid >> 5;     // 0..4 : row-block w
    const int lane = tid & 31;
    const int g    = lane >> 2;    // groupID (0..7)
    const int t    = lane & 3;     // thread-in-group (0..3)

    uint32_t smem_u32 = (uint32_t)__cvta_generic_to_shared(&sbuf[0][0]);

    const int m0  = warp * 16;
    // symmetric block-pair decomposition: row-block w vs col-blocks {w, w+1, w+2} mod 5
    const int bj0 = warp;
    const int bj1 = (warp + 1) % 5;
    const int bj2 = (warp + 2) % 5;

    float d[3][2][4];
    #pragma unroll
    for (int b = 0; b < 3; b++)
        #pragma unroll
        for (int n = 0; n < 2; n++)
            #pragma unroll
            for (int q = 0; q < 4; q++) d[b][n][q] = 0.0f;

    const int numTiles = (batch + KB - 1) / KB;

    // cp.async per-thread geometry: 640 16B chunks over 160 threads -> 4 each
    // idx = tid + p*160 ; item = idx/20 ; c4 = idx%20 (16B units along class dim)

#define ISSUE_TILE(T, S) do {                                                     \
        if ((T) < numTiles) {                                                     \
            const float* gb_ = label + (long long)(T) * KB * C;                   \
            const uint32_t sb_ = smem_u32 + (uint32_t)((S) * STAGE_BYTES);        \
            _Pragma("unroll")                                                     \
            for (int p_ = 0; p_ < 4; p_++) {                                      \
                int idx_  = tid + p_ * NTHREADS;                                  \
                int item_ = idx_ / 20;                                            \
                int c4_   = idx_ % 20;                                            \
                uint32_t sa_ = sb_ + (uint32_t)(item_ * (PITCH_F * 4) + c4_ * 16);\
                if ((T) * KB + item_ < batch) {                                   \
                    const float* ga_ = gb_ + (long long)item_ * C + c4_ * 4;      \
                    asm volatile("cp.async.cg.shared.global [%0], [%1], 16;"      \
                                 :: "r"(sa_), "l"(ga_) : "memory");               \
                } else {                                                          \
                    asm volatile("st.shared.v4.u32 [%0], {%1,%1,%1,%1};"          \
                                 :: "r"(sa_), "r"(0u) : "memory");                \
                }                                                                 \
            }                                                                     \
        }                                                                         \
    } while (0)

    int tile = blockIdx.x;
    // prologue: stages 0,1 <- tiles b, b+GRID
    ISSUE_TILE(tile, 0);
    asm volatile("cp.async.commit_group;" ::: "memory");
    ISSUE_TILE(tile + GRID, 1);
    asm volatile("cp.async.commit_group;" ::: "memory");

    int it = 0;
    while (tile < numTiles) {
        asm volatile("cp.async.wait_group 1;" ::: "memory");  // group 'it' landed (own)
        __syncthreads();   // all threads past wait -> stage it%4 fully visible;
                           // all warps done computing tile it-1 -> stage (it+2)%4 free

        ISSUE_TILE(tile + 2 * GRID, (it + 2) & 3);
        asm volatile("cp.async.commit_group;" ::: "memory");

        // ---- compute on stage it%4 : tf32 MMA straight from f32 tile ----
        const uint32_t sbase = smem_u32 + (uint32_t)((it & 3) * STAGE_BYTES);
        #pragma unroll
        for (int ks = 0; ks < KB / 8; ks++) {
            const uint32_t rowb = sbase + (uint32_t)(((ks * 8 + t) * PITCH_F) * 4);

            uint32_t a0, a1, a2, a3;
            {
                const uint32_t ab = rowb + (uint32_t)((m0 + g) * 4);
                asm volatile("ld.shared.b32 %0, [%1];"        : "=r"(a0) : "r"(ab));
                asm volatile("ld.shared.b32 %0, [%1+32];"     : "=r"(a1) : "r"(ab));
                asm volatile("ld.shared.b32 %0, [%1+1408];"   : "=r"(a2) : "r"(ab));
                asm volatile("ld.shared.b32 %0, [%1+1440];"   : "=r"(a3) : "r"(ab));
            }

            const int bjs[3] = {bj0, bj1, bj2};
            #pragma unroll
            for (int b = 0; b < 3; b++) {
                const uint32_t bb = rowb + (uint32_t)((bjs[b] * 16 + g) * 4);
                uint32_t b0, b1, b2, b3;
                asm volatile("ld.shared.b32 %0, [%1];"      : "=r"(b0) : "r"(bb));
                asm volatile("ld.shared.b32 %0, [%1+1408];" : "=r"(b1) : "r"(bb));
                asm volatile("ld.shared.b32 %0, [%1+32];"   : "=r"(b2) : "r"(bb));
                asm volatile("ld.shared.b32 %0, [%1+1440];" : "=r"(b3) : "r"(bb));
                asm volatile(
                    "mma.sync.aligned.m16n8k8.row.col.f32.tf32.tf32.f32 "
                    "{%0,%1,%2,%3}, {%4,%5,%6,%7}, {%8,%9}, {%0,%1,%2,%3};\n"
                    : "+f"(d[b][0][0]), "+f"(d[b][0][1]), "+f"(d[b][0][2]), "+f"(d[b][0][3])
                    : "r"(a0), "r"(a1), "r"(a2), "r"(a3), "r"(b0), "r"(b1));
                asm volatile(
                    "mma.sync.aligned.m16n8k8.row.col.f32.tf32.tf32.f32 "
                    "{%0,%1,%2,%3}, {%4,%5,%6,%7}, {%8,%9}, {%0,%1,%2,%3};\n"
                    : "+f"(d[b][1][0]), "+f"(d[b][1][1]), "+f"(d[b][1][2]), "+f"(d[b][1][3])
                    : "r"(a0), "r"(a1), "r"(a2), "r"(a3), "r"(b2), "r"(b3));
            }
        }
        tile += GRID;
        it++;
    }

    // ---- flush partials (integer-valued f32 -> exact, order-independent) ----
    {
        const int bjs[3] = {bj0, bj1, bj2};
        #pragma unroll
        for (int b = 0; b < 3; b++) {
            const int row = m0 + g;
            #pragma unroll
            for (int n = 0; n < 2; n++) {
                const int col = bjs[b] * 16 + n * 8 + 2 * t;
                atomicAdd(&g_cooc[(row)     * C + col],     d[b][n][0]);
                atomicAdd(&g_cooc[(row)     * C + col + 1], d[b][n][1]);
                atomicAdd(&g_cooc[(row + 8) * C + col],     d[b][n][2]);
                atomicAdd(&g_cooc[(row + 8) * C + col + 1], d[b][n][3]);
            }
        }
    }

    // ---- last-CTA finalize ----
    __threadfence();
    __syncthreads();
    if (tid == 0)
        s_last = (atomicAdd(&g_count, 1u) == (unsigned)gridDim.x - 1u) ? 1 : 0;
    __syncthreads();
    if (!s_last) return;

    float sum = 0.0f;
    for (int idx = tid; idx < C * C; idx += NTHREADS) {
        int i = idx / C, j = idx - i * C;
        int bi = i >> 4, bj = j >> 4;
        int dd = bj - bi; if (dd < 0) dd += 5;
        float cooc = (dd <= 2) ? g_cooc[i * C + j] : g_cooc[j * C + i];  // symmetry mirror
        float cnt  = g_cooc[i * C + i];
        float adj  = (i == j) ? 1.0f : __fdividef(cooc, cnt + 1e-7f);
        float r = fabsf(pre_adj[idx] - adj);
        sum += (r < 1.0f) ? (r * r) : (r - 0.5f);
    }
    #pragma unroll
    for (int o = 16; o > 0; o >>= 1) sum += __shfl_down_sync(0xffffffffu, sum, o);
    if (lane == 0) red[warp] = sum;
    __syncthreads();
    if (warp == 0) {
        float v = (lane < NWARPS) ? red[lane] : 0.0f;
        #pragma unroll
        for (int o = 16; o > 0; o >>= 1) v += __shfl_down_sync(0xffffffffu, v, o);
        if (lane == 0) out[0] = v / (float)(C * C);
    }
    __syncthreads();   // all g_cooc reads complete before re-zero
    for (int idx = tid; idx < C * C; idx += NTHREADS) g_cooc[idx] = 0.0f;
    if (tid == 0) g_count = 0u;
}

extern "C" void kernel_launch(void* const* d_in, const int* in_sizes, int n_in,
                              void* d_out, int out_size) {
    const float* pre_adj = (const float*)d_in[0];
    const float* label   = (const float*)d_in[1];
    const int batch = in_sizes[1] / C;

    fused_kernel<<<GRID, NTHREADS>>>(label, pre_adj, (float*)d_out, batch);
}

// round 11
// speedup vs baseline: 1.3404x; 1.3404x over previous
#include <cuda_runtime.h>
#include <cuda_bf16.h>
#include <cstdint>

#define C 80
#define SLAB 16                 // items per pair-slab
#define PITCH 88                // halves per item row (80+8 pad), conflict-free ldmatrix
#define SLAB_BYTES (SLAB * PITCH * 2)   // 2816
#define NTHREADS 256            // 8 warps = 4 pairs
#define GRID 296                // 2 CTAs/SM x 148
#define NGROUPS (GRID * 4)      // independent slab streams

__device__ float g_cooc[C * C];
__device__ unsigned int g_count;

__device__ const int g_pbi[15] = {0,0,0,0,0,1,1,1, 1,2,2,2,3,3,4};
__device__ const int g_pbj[15] = {0,1,2,3,4,1,2,3, 4,2,3,4,3,4,4};

#define LDSM4T(r0,r1,r2,r3,addr) \
    asm volatile("ldmatrix.sync.aligned.m8n8.x4.trans.shared.b16 {%0,%1,%2,%3}, [%4];" \
                 : "=r"(r0), "=r"(r1), "=r"(r2), "=r"(r3) : "r"(addr))

#define MMA16(acc, A0,A1,A2,A3, B0,B1) \
    asm volatile("mma.sync.aligned.m16n8k16.row.col.f32.bf16.bf16.f32 " \
                 "{%0,%1,%2,%3}, {%4,%5,%6,%7}, {%8,%9}, {%0,%1,%2,%3};" \
                 : "+f"(acc[0]), "+f"(acc[1]), "+f"(acc[2]), "+f"(acc[3]) \
                 : "r"(A0), "r"(A1), "r"(A2), "r"(A3), "r"(B0), "r"(B1))

#define PAIR_MMA(P, A0,A1,A2,A3, FB) do { \
        MMA16(d[P][0], A0,A1,A2,A3, FB[0], FB[1]); \
        MMA16(d[P][1], A0,A1,A2,A3, FB[2], FB[3]); } while (0)

static __device__ __forceinline__ uint32_t pack_bf16x2(float x, float y) {
    uint32_t r;
    asm("prmt.b32 %0, %1, %2, 0x7632;" : "=r"(r)
        : "r"(__float_as_uint(x)), "r"(__float_as_uint(y)));
    return r;
}

__global__ __launch_bounds__(NTHREADS, 2)
void fused_kernel(const float* __restrict__ label,
                  const float* __restrict__ pre_adj,
                  float* __restrict__ out, int batch) {
    __shared__ __align__(16) __nv_bfloat16 slab[4 * 2 * SLAB * PITCH];  // 4 pairs x 2 bufs
    __shared__ float sRed[15 * 256];                                     // 15 KB block accum
    __shared__ float red[8];
    __shared__ int s_last;

    const int tid    = threadIdx.x;
    const int warp   = tid >> 5;        // 0..7
    const int lane   = tid & 31;
    const int h      = warp & 1;        // half within pair
    const int pairId = warp >> 1;       // 0..3
    const int g      = lane >> 2;
    const int t      = lane & 3;
    const int gi     = lane >> 3;
    const int li     = lane & 7;

    // zero per-CTA block accumulator
    for (int i = tid; i < 15 * 256; i += NTHREADS) sRed[i] = 0.0f;
    __syncthreads();

    const uint32_t smem_u32 = (uint32_t)__cvta_generic_to_shared(slab);
    const uint32_t mybufs   = smem_u32 + (uint32_t)(pairId * 2 * SLAB_BYTES);

    // ldmatrix per-lane offsets (bytes), proven geometry (R2-R8)
    const uint32_t a_off = (uint32_t)(((((gi & 2) ? 8 : 0) + li) * PITCH + ((gi & 1) ? 8 : 0)) * 2);
    const uint32_t b_off = (uint32_t)(((((gi & 1) ? 8 : 0) + li) * PITCH + ((gi & 2) ? 8 : 0)) * 2);

    // load/store geometry: this warp fills items h*8 .. h*8+7 (8 items x 20 chunks)
    // gmem chunk = 16B of f32 (4 values); smem chunk = 8B of bf16
    int item_p[5], goff[5], soff[5];
    #pragma unroll
    for (int p = 0; p < 5; p++) {
        int chunk = lane + p * 32;
        item_p[p] = h * 8 + chunk / 20;
        int c4    = chunk % 20;
        goff[p] = item_p[p] * C + c4 * 4;
        soff[p] = item_p[p] * (PITCH * 2) + c4 * 8;   // bytes (FIXED: bf16 -> 8B per chunk)
    }

    float d[8][2][4];
    #pragma unroll
    for (int p = 0; p < 8; p++)
        #pragma unroll
        for (int n = 0; n < 2; n++)
            #pragma unroll
            for (int q = 0; q < 4; q++) d[p][n][q] = 0.0f;

    const int numSlabs = (batch + SLAB - 1) / SLAB;
    int s = blockIdx.x * 4 + pairId;

    float4 st[5];
    if (s < numSlabs) {
        const float* pb = label + (long long)s * SLAB * C;
        #pragma unroll
        for (int p = 0; p < 5; p++)
            st[p] = (s * SLAB + item_p[p] < batch) ? *(const float4*)(pb + goff[p])
                                                   : make_float4(0.f, 0.f, 0.f, 0.f);
    }

    int pbuf = 0;
    while (s < numSlabs) {
        // ---- convert + store own 8 items into pair buffer ----
        const uint32_t sb = mybufs + (uint32_t)(pbuf * SLAB_BYTES);
        #pragma unroll
        for (int p = 0; p < 5; p++) {
            uint32_t lo = pack_bf16x2(st[p].x, st[p].y);
            uint32_t hi = pack_bf16x2(st[p].z, st[p].w);
            asm volatile("st.shared.v2.b32 [%0], {%1,%2};"
                         :: "r"(sb + (uint32_t)soff[p]), "r"(lo), "r"(hi) : "memory");
        }

        // ---- prefetch next slab (fire-and-forget, ~1 slab-period of slack) ----
        const int nxt = s + NGROUPS;
        if (nxt < numSlabs) {
            const float* pb = label + (long long)nxt * SLAB * C;
            #pragma unroll
            for (int p = 0; p < 5; p++)
                st[p] = (nxt * SLAB + item_p[p] < batch) ? *(const float4*)(pb + goff[p])
                                                         : make_float4(0.f, 0.f, 0.f, 0.f);
        }

        // ---- pair-local sync: both halves stored, partner's previous MMA done ----
        asm volatile("bar.sync %0, 64;" :: "r"(pairId + 1) : "memory");

        // ---- MMA: warp h computes its 8/7 symmetric block-pairs, K=16 ----
        if (h == 0) {
            uint32_t A0[4], A1[4], fb[4];
            LDSM4T(A0[0], A0[1], A0[2], A0[3], sb + a_off + 0 * 32);
            LDSM4T(A1[0], A1[1], A1[2], A1[3], sb + a_off + 1 * 32);
            LDSM4T(fb[0], fb[1], fb[2], fb[3], sb + b_off + 0 * 32);
            PAIR_MMA(0, A0[0], A0[1], A0[2], A0[3], fb);                 // (0,0)
            LDSM4T(fb[0], fb[1], fb[2], fb[3], sb + b_off + 1 * 32);
            PAIR_MMA(1, A0[0], A0[1], A0[2], A0[3], fb);                 // (0,1)
            PAIR_MMA(5, A1[0], A1[1], A1[2], A1[3], fb);                 // (1,1)
            LDSM4T(fb[0], fb[1], fb[2], fb[3], sb + b_off + 2 * 32);
            PAIR_MMA(2, A0[0], A0[1], A0[2], A0[3], fb);                 // (0,2)
            PAIR_MMA(6, A1[0], A1[1], A1[2], A1[3], fb);                 // (1,2)
            LDSM4T(fb[0], fb[1], fb[2], fb[3], sb + b_off + 3 * 32);
            PAIR_MMA(3, A0[0], A0[1], A0[2], A0[3], fb);                 // (0,3)
            PAIR_MMA(7, A1[0], A1[1], A1[2], A1[3], fb);                 // (1,3)
            LDSM4T(fb[0], fb[1], fb[2], fb[3], sb + b_off + 4 * 32);
            PAIR_MMA(4, A0[0], A0[1], A0[2], A0[3], fb);                 // (0,4)
        } else {
            uint32_t A1[4], A2[4], A3[4], A4[4], fb[4];
            LDSM4T(A1[0], A1[1], A1[2], A1[3], sb + a_off + 1 * 32);
            LDSM4T(A2[0], A2[1], A2[2], A2[3], sb + a_off + 2 * 32);
            LDSM4T(A3[0], A3[1], A3[2], A3[3], sb + a_off + 3 * 32);
            LDSM4T(A4[0], A4[1], A4[2], A4[3], sb + a_off + 4 * 32);
            LDSM4T(fb[0], fb[1], fb[2], fb[3], sb + b_off + 2 * 32);
            PAIR_MMA(1, A2[0], A2[1], A2[2], A2[3], fb);                 // (2,2)
            LDSM4T(fb[0], fb[1], fb[2], fb[3], sb + b_off + 3 * 32);
            PAIR_MMA(2, A2[0], A2[1], A2[2], A2[3], fb);                 // (2,3)
            PAIR_MMA(4, A3[0], A3[1], A3[2], A3[3], fb);                 // (3,3)
            LDSM4T(fb[0], fb[1], fb[2], fb[3], sb + b_off + 4 * 32);
            PAIR_MMA(0, A1[0], A1[1], A1[2], A1[3], fb);                 // (1,4)
            PAIR_MMA(3, A2[0], A2[1], A2[2], A2[3], fb);                 // (2,4)
            PAIR_MMA(5, A3[0], A3[1], A3[2], A3[3], fb);                 // (3,4)
            PAIR_MMA(6, A4[0], A4[1], A4[2], A4[3], fb);                 // (4,4)
        }

        pbuf ^= 1;
        s = nxt;
    }

    // ---- flush per-warp accumulators into per-CTA smem blocks (exact ints) ----
    {
        const int npair = h ? 7 : 8;
        #pragma unroll
        for (int p = 0; p < 8; p++) {
            if (p >= npair) break;
            const int slot = (h ? 8 + p : p) * 256;
            #pragma unroll
            for (int n = 0; n < 2; n++) {
                const int cb = n * 8 + 2 * t;
                atomicAdd(&sRed[slot + (g)     * 16 + cb],     d[p][n][0]);
                atomicAdd(&sRed[slot + (g)     * 16 + cb + 1], d[p][n][1]);
                atomicAdd(&sRed[slot + (g + 8) * 16 + cb],     d[p][n][2]);
                atomicAdd(&sRed[slot + (g + 8) * 16 + cb + 1], d[p][n][3]);
            }
        }
    }
    __syncthreads();

    // ---- one global flush per CTA (4x fewer global atomics) ----
    for (int idx = tid; idx < 15 * 256; idx += NTHREADS) {
        const int slot = idx >> 8, e = idx & 255;
        const int i = g_pbi[slot] * 16 + (e >> 4);
        const int j = g_pbj[slot] * 16 + (e & 15);
        atomicAdd(&g_cooc[i * C + j], sRed[idx]);
    }

    // ---- last-CTA finalize ----
    __threadfence();
    __syncthreads();
    if (tid == 0)
        s_last = (atomicAdd(&g_count, 1u) == (unsigned)gridDim.x - 1u) ? 1 : 0;
    __syncthreads();
    if (!s_last) return;

    float sum = 0.0f;
    for (int idx = tid; idx < C * C; idx += NTHREADS) {
        int i = idx / C, j = idx - i * C;
        int bi = i >> 4, bj = j >> 4;
        float cooc = (bi <= bj) ? g_cooc[i * C + j] : g_cooc[j * C + i];  // upper blocks stored
        float cnt  = g_cooc[i * C + i];
        float adj  = (i == j) ? 1.0f : __fdividef(cooc, cnt + 1e-7f);
        float r = fabsf(pre_adj[idx] - adj);
        sum += (r < 1.0f) ? (r * r) : (r - 0.5f);
    }
    #pragma unroll
    for (int o = 16; o > 0; o >>= 1) sum += __shfl_down_sync(0xffffffffu, sum, o);
    if (lane == 0) red[warp] = sum;
    __syncthreads();
    if (warp == 0) {
        float v = (lane < 8) ? red[lane] : 0.0f;
        #pragma unroll
        for (int o = 16; o > 0; o >>= 1) v += __shfl_down_sync(0xffffffffu, v, o);
        if (lane == 0) out[0] = v / (float)(C * C);
    }
    __syncthreads();   // all g_cooc reads complete before re-zero
    for (int idx = tid; idx < C * C; idx += NTHREADS) g_cooc[idx] = 0.0f;
    if (tid == 0) g_count = 0u;
}

extern "C" void kernel_launch(void* const* d_in, const int* in_sizes, int n_in,
                              void* d_out, int out_size) {
    const float* pre_adj = (const float*)d_in[0];
    const float* label   = (const float*)d_in[1];
    const int batch = in_sizes[1] / C;

    fused_kernel<<<GRID, NTHREADS>>>(label, pre_adj, (float*)d_out, batch);
}